// round 1
// baseline (speedup 1.0000x reference)
#include <cuda_runtime.h>
#include <math.h>

// Problem constants
#define B_   4
#define S_   2048
#define D_   1024
#define H_   16
#define HD_  64
#define WIN_ 128
#define M_   (B_ * S_)   // 8192 rows

typedef unsigned long long ull;

// Scratch: Q/K/V in [B, H, S, hd] layout (static device arrays — allocation-free rule)
__device__ float g_q[M_ * D_];
__device__ float g_k[M_ * D_];
__device__ float g_v[M_ * D_];

// ---------------- packed f32x2 helpers (Blackwell FFMA2 path) ----------------
__device__ __forceinline__ ull ffma2(ull a, ull b, ull c) {
    ull d;
    asm("fma.rn.f32x2 %0, %1, %2, %3;" : "=l"(d) : "l"(a), "l"(b), "l"(c));
    return d;
}
__device__ __forceinline__ ull pack_dup(float x) {
    ull r;
    unsigned u = __float_as_uint(x);
    asm("mov.b64 %0, {%1, %1};" : "=l"(r) : "r"(u));
    return r;
}
__device__ __forceinline__ float2 unpack2(ull a) {
    unsigned lo, hi;
    asm("mov.b64 {%0, %1}, %2;" : "=r"(lo), "=r"(hi) : "l"(a));
    return make_float2(__uint_as_float(lo), __uint_as_float(hi));
}

// ---------------------------------------------------------------------------
// QKV GEMM: Y = X[8192,1024] @ W[1024,1024] + b, scattered into [B,H,S,hd].
// 128x128 tile, BK=8, 256 threads, 8x8 micro-tile per thread using FFMA2.
// grid.z selects {Q, K, V}.
// ---------------------------------------------------------------------------
__global__ __launch_bounds__(256) void qkv_gemm_kernel(
    const float* __restrict__ X,
    const float* __restrict__ Wq, const float* __restrict__ bq,
    const float* __restrict__ Wk, const float* __restrict__ bk,
    const float* __restrict__ Wv, const float* __restrict__ bv)
{
    __shared__ float As[8][132];   // transposed A tile, padded (132*4B = 16B-mult, bank-safe)
    __shared__ float Bs[8][128];

    const float* Wm; const float* bias; float* out;
    if (blockIdx.z == 0)      { Wm = Wq; bias = bq; out = g_q; }
    else if (blockIdx.z == 1) { Wm = Wk; bias = bk; out = g_k; }
    else                      { Wm = Wv; bias = bv; out = g_v; }

    const int tid  = threadIdx.x;
    const int row0 = blockIdx.y * 128;
    const int col0 = blockIdx.x * 128;
    const int tr   = tid >> 4;   // 0..15
    const int tc   = tid & 15;   // 0..15

    const int a_row = tid >> 1;          // 0..127
    const int a_col = (tid & 1) << 2;    // 0 or 4
    const int b_row = tid >> 5;          // 0..7
    const int b_col = (tid & 31) << 2;   // 0..124

    const float* Aptr = X  + (size_t)(row0 + a_row) * D_ + a_col;
    const float* Bptr = Wm + (size_t)b_row * D_ + col0 + b_col;

    ull acc[8][4];
    #pragma unroll
    for (int i = 0; i < 8; i++)
        #pragma unroll
        for (int j = 0; j < 4; j++) acc[i][j] = 0ull;

    for (int k0 = 0; k0 < D_; k0 += 8) {
        float4 av  = *(const float4*)(Aptr + k0);
        float4 bv4 = *(const float4*)(Bptr + (size_t)k0 * D_);
        As[a_col + 0][a_row] = av.x;
        As[a_col + 1][a_row] = av.y;
        As[a_col + 2][a_row] = av.z;
        As[a_col + 3][a_row] = av.w;
        *(float4*)&Bs[b_row][b_col] = bv4;
        __syncthreads();

        #pragma unroll
        for (int k = 0; k < 8; k++) {
            float4 alo = *(const float4*)&As[k][tr * 4];
            float4 ahi = *(const float4*)&As[k][64 + tr * 4];
            ulonglong2 bl = *(const ulonglong2*)&Bs[k][tc * 4];
            ulonglong2 bh = *(const ulonglong2*)&Bs[k][64 + tc * 4];
            ull bb[4] = { bl.x, bl.y, bh.x, bh.y };
            float al[4] = { alo.x, alo.y, alo.z, alo.w };
            float ah[4] = { ahi.x, ahi.y, ahi.z, ahi.w };
            #pragma unroll
            for (int i = 0; i < 4; i++) {
                ull a2 = pack_dup(al[i]);
                #pragma unroll
                for (int j = 0; j < 4; j++) acc[i][j] = ffma2(a2, bb[j], acc[i][j]);
            }
            #pragma unroll
            for (int i = 0; i < 4; i++) {
                ull a2 = pack_dup(ah[i]);
                #pragma unroll
                for (int j = 0; j < 4; j++) acc[4 + i][j] = ffma2(a2, bb[j], acc[4 + i][j]);
            }
        }
        __syncthreads();
    }

    // Epilogue: bias add + scatter into [B, H, S, hd]
    #pragma unroll
    for (int i = 0; i < 8; i++) {
        int m = row0 + ((i < 4) ? (tr * 4 + i) : (64 + tr * 4 + (i - 4)));
        int bidx = m >> 11;        // / 2048
        int s    = m & 2047;
        #pragma unroll
        for (int j = 0; j < 4; j++) {
            int c = (j < 2) ? (tc * 4 + 2 * j) : (64 + tc * 4 + 2 * (j - 2));
            int n = col0 + c;                 // even, never crosses a 64-col head boundary
            float2 v = unpack2(acc[i][j]);
            int h0 = n >> 6, d0 = n & 63;
            float* op = out + (((size_t)(bidx * H_ + h0) * S_ + s) * HD_ + d0);
            op[0] = v.x + bias[n];
            op[1] = v.y + bias[n + 1];
        }
    }
}

// ---------------------------------------------------------------------------
// Sliding-window attention: 1 thread = 1 query (64-dim acc in regs).
// Block = 128 queries of one (b,h). K/V streamed via smem in 32-key chunks.
// Chunked two-pass online softmax (logits parked in smem, one rescale/chunk).
// ---------------------------------------------------------------------------
__global__ __launch_bounds__(128) void attn_kernel(float* __restrict__ out)
{
    __shared__ float Ks[32][64];
    __shared__ float Vs[32][64];
    __shared__ float Ls[32][128];

    const int tid = threadIdx.x;
    const int bh  = blockIdx.y;            // b*H + h
    const int q0  = blockIdx.x * 128;
    const int qi  = q0 + tid;

    const float* qrow = g_q + ((size_t)bh * S_ + qi) * HD_;
    float qreg[64];
    #pragma unroll
    for (int i = 0; i < 16; i++) *(float4*)&qreg[i * 4] = *(const float4*)&qrow[i * 4];

    float mval = -INFINITY, lval = 0.f;
    float acc[64];
    #pragma unroll
    for (int i = 0; i < 64; i++) acc[i] = 0.f;

    const int kstart = max(0, q0 - WIN_);
    const int kend   = min(S_, q0 + 128 + WIN_);   // bounds are multiples of 32
    const float* kbase = g_k + (size_t)bh * S_ * HD_;
    const float* vbase = g_v + (size_t)bh * S_ * HD_;

    for (int kc = kstart; kc < kend; kc += 32) {
        __syncthreads();
        #pragma unroll
        for (int t = tid; t < 512; t += 128) {      // 32 rows * 16 float4
            int r = t >> 4, c4 = (t & 15) << 2;
            *(float4*)&Ks[r][c4] = *(const float4*)&kbase[(size_t)(kc + r) * HD_ + c4];
            *(float4*)&Vs[r][c4] = *(const float4*)&vbase[(size_t)(kc + r) * HD_ + c4];
        }
        __syncthreads();

        // Pass 1: logits + chunk max
        float cmax = -INFINITY;
        #pragma unroll 4
        for (int j = 0; j < 32; j++) {
            float s = 0.f;
            #pragma unroll
            for (int d4 = 0; d4 < 16; d4++) {
                float4 kv = *(const float4*)&Ks[j][d4 * 4];
                s += qreg[d4 * 4 + 0] * kv.x + qreg[d4 * 4 + 1] * kv.y
                   + qreg[d4 * 4 + 2] * kv.z + qreg[d4 * 4 + 3] * kv.w;
            }
            s *= 0.125f;                           // 1/sqrt(64)
            int dist = (kc + j) - qi;
            if (dist < -WIN_ || dist > WIN_) s = -INFINITY;
            Ls[j][tid] = s;
            cmax = fmaxf(cmax, s);
        }

        // One rescale per chunk
        if (cmax > mval) {
            float f = __expf(mval - cmax);         // exp(-inf)=0 handles first chunk
            lval *= f;
            #pragma unroll
            for (int i = 0; i < 64; i++) acc[i] *= f;
            mval = cmax;
        }

        // Pass 2: accumulate P·V
        if (mval > -INFINITY) {
            #pragma unroll 2
            for (int j = 0; j < 32; j++) {
                float w = __expf(Ls[j][tid] - mval);   // masked logits -> w = 0
                lval += w;
                #pragma unroll
                for (int d4 = 0; d4 < 16; d4++) {
                    float4 vv = *(const float4*)&Vs[j][d4 * 4];
                    acc[d4 * 4 + 0] += w * vv.x;
                    acc[d4 * 4 + 1] += w * vv.y;
                    acc[d4 * 4 + 2] += w * vv.z;
                    acc[d4 * 4 + 3] += w * vv.w;
                }
            }
        }
    }

    const float inv = 1.f / lval;                  // every query sees >= 1 valid key (itself)
    const int b = bh >> 4, h = bh & 15;
    float* orow = out + ((size_t)(b * S_ + qi)) * D_ + h * HD_;
    #pragma unroll
    for (int i = 0; i < 16; i++) {
        float4 o;
        o.x = acc[i * 4 + 0] * inv;
        o.y = acc[i * 4 + 1] * inv;
        o.z = acc[i * 4 + 2] * inv;
        o.w = acc[i * 4 + 3] * inv;
        *(float4*)&orow[i * 4] = o;
    }
}

// ---------------------------------------------------------------------------
extern "C" void kernel_launch(void* const* d_in, const int* in_sizes, int n_in,
                              void* d_out, int out_size)
{
    const float* X  = (const float*)d_in[0];
    const float* Wq = (const float*)d_in[1];
    const float* bq = (const float*)d_in[2];
    const float* Wk = (const float*)d_in[3];
    const float* bk = (const float*)d_in[4];
    const float* Wv = (const float*)d_in[5];
    const float* bv = (const float*)d_in[6];

    dim3 g1(D_ / 128, M_ / 128, 3);   // (8, 64, 3)
    qkv_gemm_kernel<<<g1, 256>>>(X, Wq, bq, Wk, bk, Wv, bv);

    dim3 g2(S_ / 128, B_ * H_);       // (16, 64)
    attn_kernel<<<g2, 128>>>((float*)d_out);
}

// round 4
// speedup vs baseline: 1.4856x; 1.4856x over previous
#include <cuda_runtime.h>
#include <cuda_bf16.h>
#include <math.h>
#include <stdint.h>

// ---------------- problem constants ----------------
#define B_   4
#define S_   2048
#define D_   1024
#define H_   16
#define HD_  64
#define WIN_ 128
#define M_   (B_ * S_)      // 8192

typedef unsigned long long ull;

// ---------------- scratch (static device arrays; allocation-free rule) ------
__device__ float g_q[M_ * D_];
__device__ float g_k[M_ * D_];
__device__ float g_v[M_ * D_];
__device__ __nv_bfloat16 g_x_hi[M_ * D_];
__device__ __nv_bfloat16 g_x_lo[M_ * D_];
__device__ __nv_bfloat16 g_wt_hi[3][D_ * D_];   // W transposed: [n][k]
__device__ __nv_bfloat16 g_wt_lo[3][D_ * D_];

// ---------------- packed f32x2 helpers ----------------
__device__ __forceinline__ ull ffma2(ull a, ull b, ull c) {
    ull d;
    asm("fma.rn.f32x2 %0, %1, %2, %3;" : "=l"(d) : "l"(a), "l"(b), "l"(c));
    return d;
}
__device__ __forceinline__ ull add2(ull a, ull b) {
    ull d;
    asm("add.rn.f32x2 %0, %1, %2;" : "=l"(d) : "l"(a), "l"(b));
    return d;
}
__device__ __forceinline__ ull mul2(ull a, ull b) {
    ull d;
    asm("mul.rn.f32x2 %0, %1, %2;" : "=l"(d) : "l"(a), "l"(b));
    return d;
}
__device__ __forceinline__ ull pack_dup(float x) {
    ull r; unsigned u = __float_as_uint(x);
    asm("mov.b64 %0, {%1, %1};" : "=l"(r) : "r"(u));
    return r;
}
__device__ __forceinline__ float2 unpack2(ull a) {
    unsigned lo, hi;
    asm("mov.b64 {%0, %1}, %2;" : "=r"(lo), "=r"(hi) : "l"(a));
    return make_float2(__uint_as_float(lo), __uint_as_float(hi));
}

__device__ __forceinline__ uint32_t smem_u32(const void* p) {
    uint32_t a;
    asm("{ .reg .u64 t; cvta.to.shared.u64 t, %1; cvt.u32.u64 %0, t; }" : "=r"(a) : "l"(p));
    return a;
}

#define LDSM4(r, a) \
    asm volatile("ldmatrix.sync.aligned.m8n8.x4.shared.b16 {%0,%1,%2,%3}, [%4];" \
                 : "=r"((r)[0]), "=r"((r)[1]), "=r"((r)[2]), "=r"((r)[3]) : "r"(a))
#define LDSM2(r, a) \
    asm volatile("ldmatrix.sync.aligned.m8n8.x2.shared.b16 {%0,%1}, [%2];" \
                 : "=r"((r)[0]), "=r"((r)[1]) : "r"(a))
#define MMA_BF16(c, a, b) \
    asm volatile("mma.sync.aligned.m16n8k16.row.col.f32.bf16.bf16.f32 " \
                 "{%0,%1,%2,%3}, {%4,%5,%6,%7}, {%8,%9}, {%0,%1,%2,%3};" \
                 : "+f"((c)[0]), "+f"((c)[1]), "+f"((c)[2]), "+f"((c)[3]) \
                 : "r"((a)[0]), "r"((a)[1]), "r"((a)[2]), "r"((a)[3]), "r"((b)[0]), "r"((b)[1]))

// ---------------------------------------------------------------------------
// Prep 1: X fp32 -> bf16 hi/lo
// ---------------------------------------------------------------------------
__global__ __launch_bounds__(256) void x_prep_kernel(const float* __restrict__ X)
{
    int i = (blockIdx.x * 256 + threadIdx.x) * 4;
    float4 v = *(const float4*)(X + i);
    __nv_bfloat16 h0 = __float2bfloat16(v.x), h1 = __float2bfloat16(v.y);
    __nv_bfloat16 h2 = __float2bfloat16(v.z), h3 = __float2bfloat16(v.w);
    __nv_bfloat16 l0 = __float2bfloat16(v.x - __bfloat162float(h0));
    __nv_bfloat16 l1 = __float2bfloat16(v.y - __bfloat162float(h1));
    __nv_bfloat16 l2 = __float2bfloat16(v.z - __bfloat162float(h2));
    __nv_bfloat16 l3 = __float2bfloat16(v.w - __bfloat162float(h3));
    uint2 ph, pl;
    ph.x = ((uint32_t)__bfloat16_as_ushort(h1) << 16) | __bfloat16_as_ushort(h0);
    ph.y = ((uint32_t)__bfloat16_as_ushort(h3) << 16) | __bfloat16_as_ushort(h2);
    pl.x = ((uint32_t)__bfloat16_as_ushort(l1) << 16) | __bfloat16_as_ushort(l0);
    pl.y = ((uint32_t)__bfloat16_as_ushort(l3) << 16) | __bfloat16_as_ushort(l2);
    *(uint2*)(g_x_hi + i) = ph;
    *(uint2*)(g_x_lo + i) = pl;
}

// ---------------------------------------------------------------------------
// Prep 2: transpose + split W[k][n] -> Wt_hi/lo[n][k]
// ---------------------------------------------------------------------------
__global__ __launch_bounds__(256) void wt_prep_kernel(
    const float* __restrict__ Wq, const float* __restrict__ Wk, const float* __restrict__ Wv)
{
    __shared__ float tile[32][33];
    const int z = blockIdx.z;
    const float* W = (z == 0) ? Wq : (z == 1) ? Wk : Wv;
    const int n0 = blockIdx.x * 32;
    const int k0 = blockIdx.y * 32;
    const int tx = threadIdx.x, ty = threadIdx.y;

    #pragma unroll
    for (int i = 0; i < 4; i++)
        tile[ty + 8 * i][tx] = W[(size_t)(k0 + ty + 8 * i) * D_ + n0 + tx];
    __syncthreads();
    #pragma unroll
    for (int i = 0; i < 4; i++) {
        int r = ty + 8 * i;
        float x = tile[tx][r];
        __nv_bfloat16 hi = __float2bfloat16(x);
        __nv_bfloat16 lo = __float2bfloat16(x - __bfloat162float(hi));
        size_t o = (size_t)(n0 + r) * D_ + k0 + tx;
        g_wt_hi[z][o] = hi;
        g_wt_lo[z][o] = lo;
    }
}

// ---------------------------------------------------------------------------
// QKV GEMM via mma.sync bf16, 3-pass split. Tile 128x128, KC=32, 8 warps.
// ---------------------------------------------------------------------------
#define KC    32
#define ASTR  40   // bf16 row stride (80 B) — conflict-free ldmatrix

__global__ __launch_bounds__(256) void qkv_gemm_mma(
    const float* __restrict__ bq, const float* __restrict__ bk, const float* __restrict__ bv)
{
    __shared__ __align__(16) __nv_bfloat16 Ah[128 * ASTR];
    __shared__ __align__(16) __nv_bfloat16 Al[128 * ASTR];
    __shared__ __align__(16) __nv_bfloat16 Bh[128 * ASTR];
    __shared__ __align__(16) __nv_bfloat16 Bl[128 * ASTR];

    const int z = blockIdx.z;
    const __nv_bfloat16* __restrict__ Xh = g_x_hi;
    const __nv_bfloat16* __restrict__ Xl = g_x_lo;
    const __nv_bfloat16* __restrict__ Wh = g_wt_hi[z];
    const __nv_bfloat16* __restrict__ Wl = g_wt_lo[z];
    const float* bias = (z == 0) ? bq : (z == 1) ? bk : bv;
    float* out = (z == 0) ? g_q : (z == 1) ? g_k : g_v;

    const int row0 = blockIdx.y * 128;
    const int col0 = blockIdx.x * 128;
    const int tid  = threadIdx.x;
    const int warp = tid >> 5;
    const int lane = tid & 31;
    const int wm   = warp & 1;        // 0/1 -> rows 64*wm
    const int wn   = warp >> 1;       // 0..3 -> cols 32*wn

    const uint32_t sAh = smem_u32(Ah), sAl = smem_u32(Al);
    const uint32_t sBh = smem_u32(Bh), sBl = smem_u32(Bl);

    // ldmatrix lane geometry
    const int a_row = (lane & 7) + ((lane >> 3) & 1) * 8;
    const int a_k   = ((lane >> 4) & 1) * 8;
    const int b_row = (lane & 7);
    const int b_k   = ((lane >> 3) & 1) * 8;      // lanes>=16 addr ignored by x2

    // per-thread fill coords
    const int f_m = tid >> 2;          // 0..63 (+64 on 2nd iter)
    const int f_u = tid & 3;

    float acc[4][4][4];
    #pragma unroll
    for (int tm = 0; tm < 4; tm++)
        #pragma unroll
        for (int tn = 0; tn < 4; tn++)
            #pragma unroll
            for (int r = 0; r < 4; r++) acc[tm][tn][r] = 0.f;

    uint4 pAh[2], pAl[2], pBh[2], pBl[2];

    // prologue: prefetch chunk 0
    #pragma unroll
    for (int i = 0; i < 2; i++) {
        int m = f_m + i * 64;
        size_t ga = (size_t)(row0 + m) * D_ + f_u * 8;
        size_t gb = (size_t)(col0 + m) * D_ + f_u * 8;
        pAh[i] = *(const uint4*)(Xh + ga);
        pAl[i] = *(const uint4*)(Xl + ga);
        pBh[i] = *(const uint4*)(Wh + gb);
        pBl[i] = *(const uint4*)(Wl + gb);
    }

    for (int c = 0; c < D_ / KC; c++) {
        __syncthreads();   // previous compute finished reading smem
        #pragma unroll
        for (int i = 0; i < 2; i++) {
            int m = f_m + i * 64;
            uint32_t so = (uint32_t)(m * ASTR * 2 + f_u * 16);
            *(uint4*)((char*)Ah + so) = pAh[i];
            *(uint4*)((char*)Al + so) = pAl[i];
            *(uint4*)((char*)Bh + so) = pBh[i];
            *(uint4*)((char*)Bl + so) = pBl[i];
        }
        __syncthreads();

        if (c + 1 < D_ / KC) {
            int k0n = (c + 1) * KC;
            #pragma unroll
            for (int i = 0; i < 2; i++) {
                int m = f_m + i * 64;
                size_t ga = (size_t)(row0 + m) * D_ + k0n + f_u * 8;
                size_t gb = (size_t)(col0 + m) * D_ + k0n + f_u * 8;
                pAh[i] = *(const uint4*)(Xh + ga);
                pAl[i] = *(const uint4*)(Xl + ga);
                pBh[i] = *(const uint4*)(Wh + gb);
                pBl[i] = *(const uint4*)(Wl + gb);
            }
        }

        #pragma unroll
        for (int ks = 0; ks < 2; ks++) {
            uint32_t fah[4][4], fal[4][4], fbh[4][2], fbl[4][2];
            #pragma unroll
            for (int tm = 0; tm < 4; tm++) {
                uint32_t off = (uint32_t)(((wm * 64 + tm * 16 + a_row) * ASTR + ks * 16 + a_k) * 2);
                LDSM4(fah[tm], sAh + off);
                LDSM4(fal[tm], sAl + off);
            }
            #pragma unroll
            for (int tn = 0; tn < 4; tn++) {
                uint32_t off = (uint32_t)(((wn * 32 + tn * 8 + b_row) * ASTR + ks * 16 + b_k) * 2);
                LDSM2(fbh[tn], sBh + off);
                LDSM2(fbl[tn], sBl + off);
            }
            #pragma unroll
            for (int tm = 0; tm < 4; tm++)
                #pragma unroll
                for (int tn = 0; tn < 4; tn++) {
                    MMA_BF16(acc[tm][tn], fah[tm], fbh[tn]);
                    MMA_BF16(acc[tm][tn], fah[tm], fbl[tn]);
                    MMA_BF16(acc[tm][tn], fal[tm], fbh[tn]);
                }
        }
    }

    // epilogue: scatter to [B, H, S, hd] with bias
    const int trow = lane >> 2;
    const int tcol = (lane & 3) * 2;
    #pragma unroll
    for (int tm = 0; tm < 4; tm++) {
        #pragma unroll
        for (int tn = 0; tn < 4; tn++) {
            int n = col0 + wn * 32 + tn * 8 + tcol;
            float bx = __ldg(bias + n), by = __ldg(bias + n + 1);
            int h = n >> 6, d = n & 63;
            #pragma unroll
            for (int half = 0; half < 2; half++) {
                int m = row0 + wm * 64 + tm * 16 + trow + half * 8;
                int bb = m >> 11, s = m & 2047;
                float2 o;
                o.x = acc[tm][tn][half * 2 + 0] + bx;
                o.y = acc[tm][tn][half * 2 + 1] + by;
                *(float2*)(out + (((size_t)(bb * H_ + h) * S_ + s) * HD_ + d)) = o;
            }
        }
    }
}

// ---------------------------------------------------------------------------
// Sliding-window attention, f32x2-packed math.
// ---------------------------------------------------------------------------
__global__ __launch_bounds__(128) void attn_kernel(float* __restrict__ out)
{
    __shared__ __align__(16) float Ks[32][64];
    __shared__ __align__(16) float Vs[32][64];
    __shared__ float Ls[32][128];

    const int tid = threadIdx.x;
    const int bh  = blockIdx.y;
    const int q0  = blockIdx.x * 128;
    const int qi  = q0 + tid;

    const float* qrow = g_q + ((size_t)bh * S_ + qi) * HD_;
    ull q2[32];
    #pragma unroll
    for (int i = 0; i < 16; i++) {
        ulonglong2 t = *(const ulonglong2*)&qrow[i * 4];
        q2[2 * i] = t.x; q2[2 * i + 1] = t.y;
    }

    float mval = -INFINITY, lval = 0.f;
    ull acc2[32];
    #pragma unroll
    for (int i = 0; i < 32; i++) acc2[i] = 0ull;

    const int kstart = max(0, q0 - WIN_);
    const int kend   = min(S_, q0 + 128 + WIN_);
    const float* kbase = g_k + (size_t)bh * S_ * HD_;
    const float* vbase = g_v + (size_t)bh * S_ * HD_;

    for (int kc = kstart; kc < kend; kc += 32) {
        __syncthreads();
        #pragma unroll
        for (int t = tid; t < 512; t += 128) {
            int r = t >> 4, c4 = (t & 15) << 2;
            *(float4*)&Ks[r][c4] = *(const float4*)&kbase[(size_t)(kc + r) * HD_ + c4];
            *(float4*)&Vs[r][c4] = *(const float4*)&vbase[(size_t)(kc + r) * HD_ + c4];
        }
        __syncthreads();

        // Pass 1: logits + chunk max
        float cmax = -INFINITY;
        #pragma unroll 4
        for (int j = 0; j < 32; j++) {
            const ulonglong2* kp = (const ulonglong2*)&Ks[j][0];
            ull a0 = 0, a1 = 0, a2 = 0, a3 = 0;
            #pragma unroll
            for (int i = 0; i < 8; i++) {
                ulonglong2 k0 = kp[2 * i];
                ulonglong2 k1 = kp[2 * i + 1];
                a0 = ffma2(q2[4 * i + 0], k0.x, a0);
                a1 = ffma2(q2[4 * i + 1], k0.y, a1);
                a2 = ffma2(q2[4 * i + 2], k1.x, a2);
                a3 = ffma2(q2[4 * i + 3], k1.y, a3);
            }
            a0 = add2(a0, a1); a2 = add2(a2, a3); a0 = add2(a0, a2);
            float2 u = unpack2(a0);
            float s = (u.x + u.y) * 0.125f;
            int dist = (kc + j) - qi;
            if (dist < -WIN_ || dist > WIN_) s = -INFINITY;
            Ls[j][tid] = s;
            cmax = fmaxf(cmax, s);
        }

        if (cmax > mval) {
            float f = __expf(mval - cmax);
            ull f2 = pack_dup(f);
            lval *= f;
            #pragma unroll
            for (int i = 0; i < 32; i++) acc2[i] = mul2(acc2[i], f2);
            mval = cmax;
        }

        // Pass 2: P·V
        if (mval > -INFINITY) {
            #pragma unroll 2
            for (int j = 0; j < 32; j++) {
                float w = __expf(Ls[j][tid] - mval);
                lval += w;
                ull w2 = pack_dup(w);
                const ulonglong2* vp = (const ulonglong2*)&Vs[j][0];
                #pragma unroll
                for (int i = 0; i < 16; i++) {
                    ulonglong2 vv = vp[i];
                    acc2[2 * i]     = ffma2(w2, vv.x, acc2[2 * i]);
                    acc2[2 * i + 1] = ffma2(w2, vv.y, acc2[2 * i + 1]);
                }
            }
        }
    }

    const float inv = 1.f / lval;
    const int b = bh >> 4, h = bh & 15;
    float* orow = out + ((size_t)(b * S_ + qi)) * D_ + h * HD_;
    #pragma unroll
    for (int i = 0; i < 16; i++) {
        float2 p0 = unpack2(acc2[2 * i]);
        float2 p1 = unpack2(acc2[2 * i + 1]);
        float4 o;
        o.x = p0.x * inv; o.y = p0.y * inv;
        o.z = p1.x * inv; o.w = p1.y * inv;
        *(float4*)&orow[i * 4] = o;
    }
}

// ---------------------------------------------------------------------------
extern "C" void kernel_launch(void* const* d_in, const int* in_sizes, int n_in,
                              void* d_out, int out_size)
{
    const float* X  = (const float*)d_in[0];
    const float* Wq = (const float*)d_in[1];
    const float* bq = (const float*)d_in[2];
    const float* Wk = (const float*)d_in[3];
    const float* bk = (const float*)d_in[4];
    const float* Wv = (const float*)d_in[5];
    const float* bv = (const float*)d_in[6];

    x_prep_kernel<<<M_ * D_ / 1024, 256>>>(X);

    dim3 gp(D_ / 32, D_ / 32, 3);
    wt_prep_kernel<<<gp, dim3(32, 8)>>>(Wq, Wk, Wv);

    dim3 g1(D_ / 128, M_ / 128, 3);
    qkv_gemm_mma<<<g1, 256>>>(bq, bk, bv);

    dim3 g2(S_ / 128, B_ * H_);
    attn_kernel<<<g2, 128>>>((float*)d_out);
}

// round 5
// speedup vs baseline: 2.3901x; 1.6089x over previous
#include <cuda_runtime.h>
#include <cuda_bf16.h>
#include <math.h>
#include <stdint.h>

// ---------------- problem constants ----------------
#define B_   4
#define S_   2048
#define D_   1024
#define H_   16
#define HD_  64
#define WIN_ 128
#define M_   (B_ * S_)      // 8192

// ---------------- scratch (static device arrays; allocation-free rule) ------
__device__ __nv_bfloat16 g_qh[M_ * D_], g_ql[M_ * D_];
__device__ __nv_bfloat16 g_kh[M_ * D_], g_kl[M_ * D_];
__device__ __nv_bfloat16 g_vh[M_ * D_], g_vl[M_ * D_];
__device__ __nv_bfloat16 g_x_hi[M_ * D_];
__device__ __nv_bfloat16 g_x_lo[M_ * D_];
__device__ __nv_bfloat16 g_wt_hi[3][D_ * D_];   // W transposed: [n][k]
__device__ __nv_bfloat16 g_wt_lo[3][D_ * D_];

// ---------------- helpers ----------------
__device__ __forceinline__ uint32_t smem_u32(const void* p) {
    uint32_t a;
    asm("{ .reg .u64 t; cvta.to.shared.u64 t, %1; cvt.u32.u64 %0, t; }" : "=r"(a) : "l"(p));
    return a;
}
__device__ __forceinline__ void split2(float x, float y, uint32_t& hi, uint32_t& lo) {
    __nv_bfloat16 hx = __float2bfloat16(x), hy = __float2bfloat16(y);
    __nv_bfloat16 lx = __float2bfloat16(x - __bfloat162float(hx));
    __nv_bfloat16 ly = __float2bfloat16(y - __bfloat162float(hy));
    hi = ((uint32_t)__bfloat16_as_ushort(hy) << 16) | __bfloat16_as_ushort(hx);
    lo = ((uint32_t)__bfloat16_as_ushort(ly) << 16) | __bfloat16_as_ushort(lx);
}

#define LDSM4(r, a) \
    asm volatile("ldmatrix.sync.aligned.m8n8.x4.shared.b16 {%0,%1,%2,%3}, [%4];" \
                 : "=r"((r)[0]), "=r"((r)[1]), "=r"((r)[2]), "=r"((r)[3]) : "r"(a))
#define LDSM2(r, a) \
    asm volatile("ldmatrix.sync.aligned.m8n8.x2.shared.b16 {%0,%1}, [%2];" \
                 : "=r"((r)[0]), "=r"((r)[1]) : "r"(a))
#define LDSM2T(r, a) \
    asm volatile("ldmatrix.sync.aligned.m8n8.x2.trans.shared.b16 {%0,%1}, [%2];" \
                 : "=r"((r)[0]), "=r"((r)[1]) : "r"(a))
#define MMA_BF16(c, a, b) \
    asm volatile("mma.sync.aligned.m16n8k16.row.col.f32.bf16.bf16.f32 " \
                 "{%0,%1,%2,%3}, {%4,%5,%6,%7}, {%8,%9}, {%0,%1,%2,%3};" \
                 : "+f"((c)[0]), "+f"((c)[1]), "+f"((c)[2]), "+f"((c)[3]) \
                 : "r"((a)[0]), "r"((a)[1]), "r"((a)[2]), "r"((a)[3]), "r"((b)[0]), "r"((b)[1]))

// ---------------------------------------------------------------------------
// Prep 1: X fp32 -> bf16 hi/lo
// ---------------------------------------------------------------------------
__global__ __launch_bounds__(256) void x_prep_kernel(const float* __restrict__ X)
{
    int i = (blockIdx.x * 256 + threadIdx.x) * 4;
    float4 v = *(const float4*)(X + i);
    uint32_t h0, l0, h1, l1;
    split2(v.x, v.y, h0, l0);
    split2(v.z, v.w, h1, l1);
    *(uint2*)(g_x_hi + i) = make_uint2(h0, h1);
    *(uint2*)(g_x_lo + i) = make_uint2(l0, l1);
}

// ---------------------------------------------------------------------------
// Prep 2: transpose + split W[k][n] -> Wt_hi/lo[n][k]
// ---------------------------------------------------------------------------
__global__ __launch_bounds__(256) void wt_prep_kernel(
    const float* __restrict__ Wq, const float* __restrict__ Wk, const float* __restrict__ Wv)
{
    __shared__ float tile[32][33];
    const int z = blockIdx.z;
    const float* W = (z == 0) ? Wq : (z == 1) ? Wk : Wv;
    const int n0 = blockIdx.x * 32;
    const int k0 = blockIdx.y * 32;
    const int tx = threadIdx.x, ty = threadIdx.y;

    #pragma unroll
    for (int i = 0; i < 4; i++)
        tile[ty + 8 * i][tx] = W[(size_t)(k0 + ty + 8 * i) * D_ + n0 + tx];
    __syncthreads();
    #pragma unroll
    for (int i = 0; i < 4; i++) {
        int r = ty + 8 * i;
        float x = tile[tx][r];
        __nv_bfloat16 hi = __float2bfloat16(x);
        __nv_bfloat16 lo = __float2bfloat16(x - __bfloat162float(hi));
        size_t o = (size_t)(n0 + r) * D_ + k0 + tx;
        g_wt_hi[z][o] = hi;
        g_wt_lo[z][o] = lo;
    }
}

// ---------------------------------------------------------------------------
// QKV GEMM via mma.sync bf16, 3-pass split. Tile 128x128, KC=32, 8 warps.
// Epilogue stores bf16 hi/lo into [B,H,S,hd]-layout split arrays.
// ---------------------------------------------------------------------------
#define KC    32
#define ASTR  40   // bf16 row stride (80 B) — conflict-free ldmatrix

__global__ __launch_bounds__(256) void qkv_gemm_mma(
    const float* __restrict__ bq, const float* __restrict__ bk, const float* __restrict__ bv)
{
    __shared__ __align__(16) __nv_bfloat16 Ah[128 * ASTR];
    __shared__ __align__(16) __nv_bfloat16 Al[128 * ASTR];
    __shared__ __align__(16) __nv_bfloat16 Bh[128 * ASTR];
    __shared__ __align__(16) __nv_bfloat16 Bl[128 * ASTR];

    const int z = blockIdx.z;
    const __nv_bfloat16* __restrict__ Xh = g_x_hi;
    const __nv_bfloat16* __restrict__ Xl = g_x_lo;
    const __nv_bfloat16* __restrict__ Wh = g_wt_hi[z];
    const __nv_bfloat16* __restrict__ Wl = g_wt_lo[z];
    const float* bias = (z == 0) ? bq : (z == 1) ? bk : bv;
    __nv_bfloat16* outh = (z == 0) ? g_qh : (z == 1) ? g_kh : g_vh;
    __nv_bfloat16* outl = (z == 0) ? g_ql : (z == 1) ? g_kl : g_vl;

    const int row0 = blockIdx.y * 128;
    const int col0 = blockIdx.x * 128;
    const int tid  = threadIdx.x;
    const int warp = tid >> 5;
    const int lane = tid & 31;
    const int wm   = warp & 1;
    const int wn   = warp >> 1;

    const uint32_t sAh = smem_u32(Ah), sAl = smem_u32(Al);
    const uint32_t sBh = smem_u32(Bh), sBl = smem_u32(Bl);

    const int a_row = (lane & 7) + ((lane >> 3) & 1) * 8;
    const int a_k   = ((lane >> 4) & 1) * 8;
    const int b_row = (lane & 7);
    const int b_k   = ((lane >> 3) & 1) * 8;

    const int f_m = tid >> 2;
    const int f_u = tid & 3;

    float acc[4][4][4];
    #pragma unroll
    for (int tm = 0; tm < 4; tm++)
        #pragma unroll
        for (int tn = 0; tn < 4; tn++)
            #pragma unroll
            for (int r = 0; r < 4; r++) acc[tm][tn][r] = 0.f;

    uint4 pAh[2], pAl[2], pBh[2], pBl[2];
    #pragma unroll
    for (int i = 0; i < 2; i++) {
        int m = f_m + i * 64;
        size_t ga = (size_t)(row0 + m) * D_ + f_u * 8;
        size_t gb = (size_t)(col0 + m) * D_ + f_u * 8;
        pAh[i] = *(const uint4*)(Xh + ga);
        pAl[i] = *(const uint4*)(Xl + ga);
        pBh[i] = *(const uint4*)(Wh + gb);
        pBl[i] = *(const uint4*)(Wl + gb);
    }

    for (int c = 0; c < D_ / KC; c++) {
        __syncthreads();
        #pragma unroll
        for (int i = 0; i < 2; i++) {
            int m = f_m + i * 64;
            uint32_t so = (uint32_t)(m * ASTR * 2 + f_u * 16);
            *(uint4*)((char*)Ah + so) = pAh[i];
            *(uint4*)((char*)Al + so) = pAl[i];
            *(uint4*)((char*)Bh + so) = pBh[i];
            *(uint4*)((char*)Bl + so) = pBl[i];
        }
        __syncthreads();

        if (c + 1 < D_ / KC) {
            int k0n = (c + 1) * KC;
            #pragma unroll
            for (int i = 0; i < 2; i++) {
                int m = f_m + i * 64;
                size_t ga = (size_t)(row0 + m) * D_ + k0n + f_u * 8;
                size_t gb = (size_t)(col0 + m) * D_ + k0n + f_u * 8;
                pAh[i] = *(const uint4*)(Xh + ga);
                pAl[i] = *(const uint4*)(Xl + ga);
                pBh[i] = *(const uint4*)(Wh + gb);
                pBl[i] = *(const uint4*)(Wl + gb);
            }
        }

        #pragma unroll
        for (int ks = 0; ks < 2; ks++) {
            uint32_t fah[4][4], fal[4][4], fbh[4][2], fbl[4][2];
            #pragma unroll
            for (int tm = 0; tm < 4; tm++) {
                uint32_t off = (uint32_t)(((wm * 64 + tm * 16 + a_row) * ASTR + ks * 16 + a_k) * 2);
                LDSM4(fah[tm], sAh + off);
                LDSM4(fal[tm], sAl + off);
            }
            #pragma unroll
            for (int tn = 0; tn < 4; tn++) {
                uint32_t off = (uint32_t)(((wn * 32 + tn * 8 + b_row) * ASTR + ks * 16 + b_k) * 2);
                LDSM2(fbh[tn], sBh + off);
                LDSM2(fbl[tn], sBl + off);
            }
            #pragma unroll
            for (int tm = 0; tm < 4; tm++)
                #pragma unroll
                for (int tn = 0; tn < 4; tn++) {
                    MMA_BF16(acc[tm][tn], fah[tm], fbh[tn]);
                    MMA_BF16(acc[tm][tn], fah[tm], fbl[tn]);
                    MMA_BF16(acc[tm][tn], fal[tm], fbh[tn]);
                }
        }
    }

    // epilogue: bias + split-store bf16 hi/lo into [B, H, S, hd]
    const int trow = lane >> 2;
    const int tcol = (lane & 3) * 2;
    #pragma unroll
    for (int tm = 0; tm < 4; tm++) {
        #pragma unroll
        for (int tn = 0; tn < 4; tn++) {
            int n = col0 + wn * 32 + tn * 8 + tcol;
            float bx = __ldg(bias + n), by = __ldg(bias + n + 1);
            int h = n >> 6, d = n & 63;
            #pragma unroll
            for (int half = 0; half < 2; half++) {
                int m = row0 + wm * 64 + tm * 16 + trow + half * 8;
                int bb = m >> 11, s = m & 2047;
                float x = acc[tm][tn][half * 2 + 0] + bx;
                float y = acc[tm][tn][half * 2 + 1] + by;
                uint32_t ph, pl;
                split2(x, y, ph, pl);
                size_t idx = ((size_t)(bb * H_ + h) * S_ + s) * HD_ + d;
                *(uint32_t*)(outh + idx) = ph;
                *(uint32_t*)(outl + idx) = pl;
            }
        }
    }
}

// ---------------------------------------------------------------------------
// Sliding-window flash attention via mma.sync, bf16 hi/lo 3-pass.
// Block = 64 queries of one (b,h); 4 warps, each owns 16 query rows.
// ---------------------------------------------------------------------------
#define QSTR 72                     // bf16 row stride (144 B) — conflict-free ldmatrix
#define ATILE (64 * QSTR)

__global__ __launch_bounds__(128) void attn_mma_kernel(float* __restrict__ out)
{
    __shared__ __align__(16) __nv_bfloat16 sm[4 * ATILE];   // 36.9 KB
    __nv_bfloat16* Qh = sm;            // aliases Kh (Q consumed into regs first)
    __nv_bfloat16* Ql = sm + ATILE;    // aliases Kl
    __nv_bfloat16* Kh = sm;
    __nv_bfloat16* Kl = sm + ATILE;
    __nv_bfloat16* Vh = sm + 2 * ATILE;
    __nv_bfloat16* Vl = sm + 3 * ATILE;

    const int tid  = threadIdx.x;
    const int warp = tid >> 5;
    const int lane = tid & 31;
    const int bh = blockIdx.y;
    const int q0 = blockIdx.x * 64;

    const int row_f = tid >> 1;          // 0..63
    const int cb_f  = (tid & 1) * 32;

    // ---- load Q tile, build A fragments in regs ----
    {
        const __nv_bfloat16* gqh = g_qh + ((size_t)bh * S_ + q0) * HD_;
        const __nv_bfloat16* gql = g_ql + ((size_t)bh * S_ + q0) * HD_;
        #pragma unroll
        for (int i = 0; i < 4; i++) {
            *(uint4*)(Qh + row_f * QSTR + cb_f + 8 * i) = *(const uint4*)(gqh + row_f * 64 + cb_f + 8 * i);
            *(uint4*)(Ql + row_f * QSTR + cb_f + 8 * i) = *(const uint4*)(gql + row_f * 64 + cb_f + 8 * i);
        }
    }
    __syncthreads();

    const int a_row = lane & 15;
    const int a_k   = ((lane >> 4) & 1) * 8;
    uint32_t qfh[4][4], qfl[4][4];
    #pragma unroll
    for (int ks = 0; ks < 4; ks++) {
        uint32_t off = (uint32_t)(((16 * warp + a_row) * QSTR + ks * 16 + a_k) * 2);
        LDSM4(qfh[ks], smem_u32(Qh) + off);
        LDSM4(qfl[ks], smem_u32(Ql) + off);
    }

    float accO[8][4];
    #pragma unroll
    for (int n = 0; n < 8; n++)
        #pragma unroll
        for (int r = 0; r < 4; r++) accO[n][r] = 0.f;
    float m0 = -INFINITY, m1 = -INFINITY, l0 = 0.f, l1 = 0.f;

    const int tr = lane >> 2;
    const int tc = (lane & 3) * 2;
    const int b_row = lane & 7;
    const int b_k   = ((lane >> 3) & 1) * 8;
    const int v_lrow = lane & 15;

    const int kstart = max(0, q0 - WIN_);
    const int kend   = min(S_, q0 + 64 + WIN_);
    const __nv_bfloat16* gkh = g_kh + (size_t)bh * S_ * HD_;
    const __nv_bfloat16* gkl = g_kl + (size_t)bh * S_ * HD_;
    const __nv_bfloat16* gvh = g_vh + (size_t)bh * S_ * HD_;
    const __nv_bfloat16* gvl = g_vl + (size_t)bh * S_ * HD_;

    for (int kc = kstart; kc < kend; kc += 64) {
        __syncthreads();   // everyone done with previous K/V (and Q frags on iter 0)
        #pragma unroll
        for (int i = 0; i < 4; i++) {
            size_t g = (size_t)(kc + row_f) * 64 + cb_f + 8 * i;
            uint32_t so = (uint32_t)(row_f * QSTR + cb_f + 8 * i);
            *(uint4*)(Kh + so) = *(const uint4*)(gkh + g);
            *(uint4*)(Kl + so) = *(const uint4*)(gkl + g);
            *(uint4*)(Vh + so) = *(const uint4*)(gvh + g);
            *(uint4*)(Vl + so) = *(const uint4*)(gvl + g);
        }
        __syncthreads();

        // ---- S = Q K^T (3-pass) ----
        float S[8][4];
        #pragma unroll
        for (int n = 0; n < 8; n++)
            #pragma unroll
            for (int r = 0; r < 4; r++) S[n][r] = 0.f;

        #pragma unroll
        for (int ks = 0; ks < 4; ks++) {
            #pragma unroll
            for (int n = 0; n < 8; n++) {
                uint32_t kfh[2], kfl2[2];
                uint32_t off = (uint32_t)(((8 * n + b_row) * QSTR + ks * 16 + b_k) * 2);
                LDSM2(kfh, smem_u32(Kh) + off);
                LDSM2(kfl2, smem_u32(Kl) + off);
                MMA_BF16(S[n], qfh[ks], kfh);
                MMA_BF16(S[n], qfh[ks], kfl2);
                MMA_BF16(S[n], qfl[ks], kfh);
            }
        }

        // ---- scale + mask (only first/last chunk can clip the window) ----
        const bool needmask = (kc < q0 - 64) || (kc > q0 + 64);
        #pragma unroll
        for (int n = 0; n < 8; n++)
            #pragma unroll
            for (int r = 0; r < 4; r++) {
                float s = S[n][r] * 0.125f;
                if (needmask) {
                    int col = kc + 8 * n + tc + (r & 1);
                    int qr  = q0 + 16 * warp + tr + ((r >> 1) * 8);
                    int dist = col - qr;
                    if (dist < -WIN_ || dist > WIN_) s = -INFINITY;
                }
                S[n][r] = s;
            }

        // ---- online softmax ----
        float c0 = -INFINITY, c1 = -INFINITY;
        #pragma unroll
        for (int n = 0; n < 8; n++) {
            c0 = fmaxf(c0, fmaxf(S[n][0], S[n][1]));
            c1 = fmaxf(c1, fmaxf(S[n][2], S[n][3]));
        }
        c0 = fmaxf(c0, __shfl_xor_sync(0xffffffffu, c0, 1));
        c0 = fmaxf(c0, __shfl_xor_sync(0xffffffffu, c0, 2));
        c1 = fmaxf(c1, __shfl_xor_sync(0xffffffffu, c1, 1));
        c1 = fmaxf(c1, __shfl_xor_sync(0xffffffffu, c1, 2));

        float nm0 = fmaxf(m0, c0), nm1 = fmaxf(m1, c1);
        float f0 = __expf(m0 - nm0), f1 = __expf(m1 - nm1);
        m0 = nm0; m1 = nm1;
        l0 *= f0; l1 *= f1;
        #pragma unroll
        for (int n = 0; n < 8; n++) {
            accO[n][0] *= f0; accO[n][1] *= f0;
            accO[n][2] *= f1; accO[n][3] *= f1;
        }

        #pragma unroll
        for (int n = 0; n < 8; n++) {
            float p0 = __expf(S[n][0] - m0);
            float p1 = __expf(S[n][1] - m0);
            float p2 = __expf(S[n][2] - m1);
            float p3 = __expf(S[n][3] - m1);
            l0 += p0 + p1; l1 += p2 + p3;
            S[n][0] = p0; S[n][1] = p1; S[n][2] = p2; S[n][3] = p3;
        }

        // ---- O += P V (3-pass), P fragments straight from S regs ----
        #pragma unroll
        for (int j = 0; j < 4; j++) {
            uint32_t pah[4], pal[4];
            split2(S[2 * j][0],     S[2 * j][1],     pah[0], pal[0]);
            split2(S[2 * j][2],     S[2 * j][3],     pah[1], pal[1]);
            split2(S[2 * j + 1][0], S[2 * j + 1][1], pah[2], pal[2]);
            split2(S[2 * j + 1][2], S[2 * j + 1][3], pah[3], pal[3]);
            #pragma unroll
            for (int n = 0; n < 8; n++) {
                uint32_t vfh[2], vfl2[2];
                uint32_t off = (uint32_t)(((16 * j + v_lrow) * QSTR + 8 * n) * 2);
                LDSM2T(vfh, smem_u32(Vh) + off);
                LDSM2T(vfl2, smem_u32(Vl) + off);
                MMA_BF16(accO[n], pah, vfh);
                MMA_BF16(accO[n], pah, vfl2);
                MMA_BF16(accO[n], pal, vfh);
            }
        }
    }

    // ---- finalize ----
    l0 += __shfl_xor_sync(0xffffffffu, l0, 1);
    l0 += __shfl_xor_sync(0xffffffffu, l0, 2);
    l1 += __shfl_xor_sync(0xffffffffu, l1, 1);
    l1 += __shfl_xor_sync(0xffffffffu, l1, 2);
    const float inv0 = 1.f / l0, inv1 = 1.f / l1;

    const int b = bh >> 4, h = bh & 15;
    const int qr0 = q0 + 16 * warp + tr;
    float* o0 = out + ((size_t)(b * S_ + qr0)) * D_ + h * HD_;
    float* o1 = out + ((size_t)(b * S_ + qr0 + 8)) * D_ + h * HD_;
    #pragma unroll
    for (int n = 0; n < 8; n++) {
        float2 u;
        u.x = accO[n][0] * inv0; u.y = accO[n][1] * inv0;
        *(float2*)(o0 + 8 * n + tc) = u;
        u.x = accO[n][2] * inv1; u.y = accO[n][3] * inv1;
        *(float2*)(o1 + 8 * n + tc) = u;
    }
}

// ---------------------------------------------------------------------------
extern "C" void kernel_launch(void* const* d_in, const int* in_sizes, int n_in,
                              void* d_out, int out_size)
{
    const float* X  = (const float*)d_in[0];
    const float* Wq = (const float*)d_in[1];
    const float* bq = (const float*)d_in[2];
    const float* Wk = (const float*)d_in[3];
    const float* bk = (const float*)d_in[4];
    const float* Wv = (const float*)d_in[5];
    const float* bv = (const float*)d_in[6];

    x_prep_kernel<<<M_ * D_ / 1024, 256>>>(X);

    dim3 gp(D_ / 32, D_ / 32, 3);
    wt_prep_kernel<<<gp, dim3(32, 8)>>>(Wq, Wk, Wv);

    dim3 g1(D_ / 128, M_ / 128, 3);
    qkv_gemm_mma<<<g1, 256>>>(bq, bk, bv);

    dim3 g2(S_ / 64, B_ * H_);
    attn_mma_kernel<<<g2, 128>>>((float*)d_out);
}